// round 2
// baseline (speedup 1.0000x reference)
#include <cuda_runtime.h>

#define B_  4
#define T_  2048
#define E_  512
#define H_  8
#define HS_ 64
#define NH  (H_ * HS_)   // 512

// ---------------- scratch (device globals; no allocation allowed) ----------
__device__ float g_q[(size_t)B_ * H_ * T_ * HS_];   // [B,H,T,HS]
__device__ float g_k[(size_t)B_ * H_ * T_ * HS_];
__device__ float g_v[(size_t)B_ * H_ * T_ * HS_];
__device__ float g_o[(size_t)B_ * T_ * NH];         // [B,T,H*HS]

// ---------------------------------------------------------------------------
// Kernel 1: fused QKV projection.
// For each (b, h, 64-row tile of T): [64,E] @ [E,64] -> three [64,64] outputs.
// One X tile in smem is reused against wq/wk/wv tiles (3x arithmetic intensity).
// blockDim = 256 (16x16), 4x4 micro-tile per thread per output.
// ---------------------------------------------------------------------------
__global__ __launch_bounds__(256)
void qkv_kernel(const float* __restrict__ x,
                const float* __restrict__ wq,
                const float* __restrict__ wk,
                const float* __restrict__ wv)
{
    __shared__ float Xs[32][65];    // transposed: Xs[k][m]
    __shared__ float Bqs[32][64];
    __shared__ float Bks[32][64];
    __shared__ float Bvs[32][64];

    const int b  = blockIdx.z;
    const int h  = blockIdx.y;
    const int m0 = blockIdx.x * 64;
    const int tid = threadIdx.x;
    const int tx = tid & 15, ty = tid >> 4;

    const float* xb  = x  + ((size_t)b * T_ + m0) * E_;
    const float* wqh = wq + (size_t)h * E_ * HS_;
    const float* wkh = wk + (size_t)h * E_ * HS_;
    const float* wvh = wv + (size_t)h * E_ * HS_;

    float aq[4][4] = {}, ak[4][4] = {}, av[4][4] = {};

    for (int kk = 0; kk < E_; kk += 32) {
        // X tile: 64 rows x 32 k, stored transposed. Coalesced 32-wide loads.
        #pragma unroll
        for (int r = 0; r < 8; r++) {
            int idx = tid + r * 256;
            int m = idx >> 5, k = idx & 31;
            Xs[k][m] = xb[(size_t)m * E_ + kk + k];
        }
        // Weight tiles: 32 k x 64 n each, coalesced 64-wide loads.
        #pragma unroll
        for (int r = 0; r < 8; r++) {
            int idx = tid + r * 256;
            int k = idx >> 6, n = idx & 63;
            int g = (kk + k) * HS_ + n;
            Bqs[k][n] = wqh[g];
            Bks[k][n] = wkh[g];
            Bvs[k][n] = wvh[g];
        }
        __syncthreads();

        #pragma unroll 8
        for (int k = 0; k < 32; k++) {
            float a[4];
            #pragma unroll
            for (int i = 0; i < 4; i++) a[i] = Xs[k][ty * 4 + i];
            float4 q4 = *(const float4*)&Bqs[k][tx * 4];
            float4 k4 = *(const float4*)&Bks[k][tx * 4];
            float4 v4 = *(const float4*)&Bvs[k][tx * 4];
            float bq[4] = {q4.x, q4.y, q4.z, q4.w};
            float bk[4] = {k4.x, k4.y, k4.z, k4.w};
            float bv[4] = {v4.x, v4.y, v4.z, v4.w};
            #pragma unroll
            for (int i = 0; i < 4; i++) {
                #pragma unroll
                for (int j = 0; j < 4; j++) {
                    aq[i][j] = fmaf(a[i], bq[j], aq[i][j]);
                    ak[i][j] = fmaf(a[i], bk[j], ak[i][j]);
                    av[i][j] = fmaf(a[i], bv[j], av[i][j]);
                }
            }
        }
        __syncthreads();
    }

    float* qo = g_q + ((size_t)(b * H_ + h) * T_ + m0) * HS_;
    float* ko = g_k + ((size_t)(b * H_ + h) * T_ + m0) * HS_;
    float* vo = g_v + ((size_t)(b * H_ + h) * T_ + m0) * HS_;
    #pragma unroll
    for (int i = 0; i < 4; i++) {
        #pragma unroll
        for (int j = 0; j < 4; j++) {
            size_t o = (size_t)(ty * 4 + i) * HS_ + tx * 4 + j;
            qo[o] = aq[i][j];
            ko[o] = ak[i][j];
            vo[o] = av[i][j];
        }
    }
}

// ---------------------------------------------------------------------------
// Kernel 2: fused causal flash attention per (b, h, 64-query tile).
// Online softmax, key tiles of 64. q-tiles launched longest-first for balance.
// Needs 66 KB smem -> dynamic smem + cudaFuncSetAttribute.
// ---------------------------------------------------------------------------
#define ATTN_SMEM_BYTES ((64 * 65 * 3 + 64 * 64) * 4)

__device__ __forceinline__ float group16_max(float v)
{
    #pragma unroll
    for (int m = 8; m >= 1; m >>= 1)
        v = fmaxf(v, __shfl_xor_sync(0xffffffffu, v, m));
    return v;
}
__device__ __forceinline__ float group16_sum(float v)
{
    #pragma unroll
    for (int m = 8; m >= 1; m >>= 1)
        v += __shfl_xor_sync(0xffffffffu, v, m);
    return v;
}

__global__ __launch_bounds__(256)
void attn_kernel()
{
    extern __shared__ float smem[];
    float (*Qs)[65] = (float(*)[65])(smem);                 // Qs[d][m]
    float (*Ks)[65] = (float(*)[65])(smem + 64 * 65);       // Ks[d][n]
    float (*Ps)[65] = (float(*)[65])(smem + 2 * 64 * 65);   // Ps[n][m]
    float (*Vs)[64] = (float(*)[64])(smem + 3 * 64 * 65);   // Vs[n][e]

    const int b = blockIdx.z, h = blockIdx.y;
    const int nqt = T_ / 64;
    const int qt = nqt - 1 - blockIdx.x;    // heavy tiles first
    const int m0 = qt * 64;
    const int tid = threadIdx.x;
    const int tx = tid & 15, ty = tid >> 4;

    const float* qp = g_q + (size_t)(b * H_ + h) * T_ * HS_;
    const float* kp = g_k + (size_t)(b * H_ + h) * T_ * HS_;
    const float* vp = g_v + (size_t)(b * H_ + h) * T_ * HS_;

    // Q tile, transposed into smem (reused for all key tiles)
    #pragma unroll
    for (int r = 0; r < 16; r++) {
        int idx = tid + r * 256;
        int m = idx >> 6, d = idx & 63;
        Qs[d][m] = qp[(size_t)(m0 + m) * HS_ + d];
    }

    float m_run[4], l_run[4], o_acc[4][4];
    #pragma unroll
    for (int i = 0; i < 4; i++) {
        m_run[i] = -1e30f;
        l_run[i] = 0.0f;
        #pragma unroll
        for (int j = 0; j < 4; j++) o_acc[i][j] = 0.0f;
    }

    for (int kt = 0; kt <= qt; kt++) {
        const int n0 = kt * 64;
        __syncthreads();   // prior iter done reading Ks/Vs/Ps (also covers Qs 1st iter)
        #pragma unroll
        for (int r = 0; r < 16; r++) {
            int idx = tid + r * 256;
            int n = idx >> 6, d = idx & 63;
            float kv = kp[(size_t)(n0 + n) * HS_ + d];
            float vv = vp[(size_t)(n0 + n) * HS_ + d];
            Ks[d][n] = kv;
            Vs[n][d] = vv;
        }
        __syncthreads();

        // S = Q K^T  (64x64x64)
        float s[4][4] = {};
        #pragma unroll 16
        for (int d = 0; d < 64; d++) {
            float a[4], bb[4];
            #pragma unroll
            for (int i = 0; i < 4; i++) a[i] = Qs[d][ty * 4 + i];
            #pragma unroll
            for (int j = 0; j < 4; j++) bb[j] = Ks[d][tx * 4 + j];
            #pragma unroll
            for (int i = 0; i < 4; i++)
                #pragma unroll
                for (int j = 0; j < 4; j++)
                    s[i][j] = fmaf(a[i], bb[j], s[i][j]);
        }

        const float scale = 0.125f;   // 1/sqrt(64)
        if (kt == qt) {
            #pragma unroll
            for (int i = 0; i < 4; i++)
                #pragma unroll
                for (int j = 0; j < 4; j++)
                    s[i][j] = (tx * 4 + j > ty * 4 + i) ? -1e30f : s[i][j] * scale;
        } else {
            #pragma unroll
            for (int i = 0; i < 4; i++)
                #pragma unroll
                for (int j = 0; j < 4; j++)
                    s[i][j] *= scale;
        }

        // online softmax (row stats across the 16 lanes sharing ty)
        float alpha[4];
        #pragma unroll
        for (int i = 0; i < 4; i++) {
            float rmax = fmaxf(fmaxf(s[i][0], s[i][1]), fmaxf(s[i][2], s[i][3]));
            rmax = group16_max(rmax);
            float mn = fmaxf(m_run[i], rmax);
            alpha[i] = __expf(m_run[i] - mn);
            m_run[i] = mn;
            float rsum = 0.0f;
            #pragma unroll
            for (int j = 0; j < 4; j++) {
                s[i][j] = __expf(s[i][j] - mn);
                rsum += s[i][j];
            }
            rsum = group16_sum(rsum);
            l_run[i] = l_run[i] * alpha[i] + rsum;
        }
        #pragma unroll
        for (int i = 0; i < 4; i++)
            #pragma unroll
            for (int j = 0; j < 4; j++)
                o_acc[i][j] *= alpha[i];

        // stage P (transposed) for the PV GEMM
        #pragma unroll
        for (int i = 0; i < 4; i++)
            #pragma unroll
            for (int j = 0; j < 4; j++)
                Ps[tx * 4 + j][ty * 4 + i] = s[i][j];
        __syncthreads();

        // O += P V  (64x64x64)
        #pragma unroll 16
        for (int n = 0; n < 64; n++) {
            float a[4];
            #pragma unroll
            for (int i = 0; i < 4; i++) a[i] = Ps[n][ty * 4 + i];
            float4 v4 = *(const float4*)&Vs[n][tx * 4];
            float bb[4] = {v4.x, v4.y, v4.z, v4.w};
            #pragma unroll
            for (int i = 0; i < 4; i++)
                #pragma unroll
                for (int j = 0; j < 4; j++)
                    o_acc[i][j] = fmaf(a[i], bb[j], o_acc[i][j]);
        }
    }

    // write O in [B,T,H*HS] layout (ready for projection)
    float* op = g_o + ((size_t)b * T_ + m0) * NH + h * HS_;
    #pragma unroll
    for (int i = 0; i < 4; i++) {
        float inv = 1.0f / l_run[i];
        #pragma unroll
        for (int j = 0; j < 4; j++)
            op[(size_t)(ty * 4 + i) * NH + tx * 4 + j] = o_acc[i][j] * inv;
    }
}

// ---------------------------------------------------------------------------
// Kernel 3: output projection  out[BT, E] = O[BT, 512] @ wp[512, E]
// ---------------------------------------------------------------------------
__global__ __launch_bounds__(256)
void proj_kernel(const float* __restrict__ wp, float* __restrict__ out)
{
    __shared__ float As[32][65];
    __shared__ float Bs[32][64];

    const int m0 = blockIdx.x * 64;
    const int n0 = blockIdx.y * 64;
    const int tid = threadIdx.x;
    const int tx = tid & 15, ty = tid >> 4;

    float acc[4][4] = {};

    for (int kk = 0; kk < NH; kk += 32) {
        #pragma unroll
        for (int r = 0; r < 8; r++) {
            int idx = tid + r * 256;
            int m = idx >> 5, k = idx & 31;
            As[k][m] = g_o[(size_t)(m0 + m) * NH + kk + k];
        }
        #pragma unroll
        for (int r = 0; r < 8; r++) {
            int idx = tid + r * 256;
            int k = idx >> 6, n = idx & 63;
            Bs[k][n] = wp[(size_t)(kk + k) * E_ + n0 + n];
        }
        __syncthreads();

        #pragma unroll 8
        for (int k = 0; k < 32; k++) {
            float a[4];
            #pragma unroll
            for (int i = 0; i < 4; i++) a[i] = As[k][ty * 4 + i];
            float4 b4 = *(const float4*)&Bs[k][tx * 4];
            float bb[4] = {b4.x, b4.y, b4.z, b4.w};
            #pragma unroll
            for (int i = 0; i < 4; i++)
                #pragma unroll
                for (int j = 0; j < 4; j++)
                    acc[i][j] = fmaf(a[i], bb[j], acc[i][j]);
        }
        __syncthreads();
    }

    #pragma unroll
    for (int i = 0; i < 4; i++)
        #pragma unroll
        for (int j = 0; j < 4; j++)
            out[(size_t)(m0 + ty * 4 + i) * E_ + n0 + tx * 4 + j] = acc[i][j];
}

// ---------------------------------------------------------------------------
extern "C" void kernel_launch(void* const* d_in, const int* in_sizes, int n_in,
                              void* d_out, int out_size)
{
    const float* x  = (const float*)d_in[0];
    const float* wq = (const float*)d_in[1];
    const float* wk = (const float*)d_in[2];
    const float* wv = (const float*)d_in[3];
    const float* wp = (const float*)d_in[4];
    float* out = (float*)d_out;

    // host-side attribute set (idempotent, capture-safe: not a stream op)
    cudaFuncSetAttribute(attn_kernel,
                         cudaFuncAttributeMaxDynamicSharedMemorySize,
                         ATTN_SMEM_BYTES);

    qkv_kernel<<<dim3(T_ / 64, H_, B_), 256>>>(x, wq, wk, wv);
    attn_kernel<<<dim3(T_ / 64, H_, B_), 256, ATTN_SMEM_BYTES>>>();
    proj_kernel<<<dim3((B_ * T_) / 64, E_ / 64), 256>>>(wp, out);
}

// round 4
// speedup vs baseline: 2.9962x; 2.9962x over previous
#include <cuda_runtime.h>
#include <cstdint>

#define B_  4
#define T_  2048
#define E_  512
#define H_  8
#define HS_ 64
#define NH  (H_ * HS_)   // 512

// ---------------- scratch (device globals; no allocation allowed) ----------
__device__ float g_q[(size_t)B_ * H_ * T_ * HS_];   // [B,H,T,HS], tf32-rounded
__device__ float g_k[(size_t)B_ * H_ * T_ * HS_];
__device__ float g_v[(size_t)B_ * H_ * T_ * HS_];
__device__ float g_o[(size_t)B_ * T_ * NH];         // [B,T,H*HS], tf32-rounded
__device__ float g_xr[(size_t)B_ * T_ * E_];        // tf32-rounded x
__device__ float g_wqkv[3 * NH * E_];               // K-major [w*512+h*64+d][e]
__device__ float g_wpT[E_ * NH];                    // K-major [n][k]

// ======================= helpers ===========================================
__device__ __forceinline__ uint32_t smem_u32(const void* p) {
    uint32_t a;
    asm("{ .reg .u64 t; cvta.to.shared.u64 t, %1; cvt.u32.u64 %0, t; }"
        : "=r"(a) : "l"(p));
    return a;
}
__device__ __forceinline__ float rna(float x) {
    uint32_t r;
    asm("cvt.rna.tf32.f32 %0, %1;" : "=r"(r) : "f"(x));
    return __uint_as_float(r);
}
// D += A(16x8 tf32 row) * B(8x8 tf32 col)
__device__ __forceinline__ void mma8(float d[4], const uint32_t a[4],
                                     const uint32_t b[2]) {
    asm volatile(
        "mma.sync.aligned.m16n8k8.row.col.f32.tf32.tf32.f32 "
        "{%0,%1,%2,%3},{%4,%5,%6,%7},{%8,%9},{%0,%1,%2,%3};"
        : "+f"(d[0]), "+f"(d[1]), "+f"(d[2]), "+f"(d[3])
        : "r"(a[0]), "r"(a[1]), "r"(a[2]), "r"(a[3]), "r"(b[0]), "r"(b[1]));
}
#define CP16(ds, sp)  asm volatile("cp.async.cg.shared.global [%0], [%1], 16;" :: "r"(ds), "l"(sp))
#define CPCOMMIT()    asm volatile("cp.async.commit_group;" ::: "memory")
#define CPWAIT0()     asm volatile("cp.async.wait_group 0;" ::: "memory")

// ======================= prep kernels ======================================
__global__ __launch_bounds__(256)
void round_x(const float* __restrict__ x)
{
    size_t i = ((size_t)blockIdx.x * 256 + threadIdx.x) * 4;
    float4 v = *(const float4*)(x + i);
    v.x = rna(v.x); v.y = rna(v.y); v.z = rna(v.z); v.w = rna(v.w);
    *(float4*)(g_xr + i) = v;
}

// g_wqkv[(w*512 + h*64 + d)][e] = rna(w_src[h][e][d])
__global__ __launch_bounds__(256)
void tr_wqkv(const float* __restrict__ wq, const float* __restrict__ wk,
             const float* __restrict__ wv)
{
    __shared__ float tt[64][65];
    const int w = blockIdx.z, h = blockIdx.y, e0 = blockIdx.x * 64;
    const float* src = (w == 0 ? wq : (w == 1 ? wk : wv)) + (size_t)h * E_ * HS_;
    const int tid = threadIdx.x;
    #pragma unroll
    for (int r = 0; r < 16; r++) {
        int idx = tid + r * 256, e = idx >> 6, d = idx & 63;
        tt[e][d] = src[(size_t)(e0 + e) * HS_ + d];
    }
    __syncthreads();
    float* dst = g_wqkv + (size_t)(w * 512 + h * 64) * E_;
    #pragma unroll
    for (int r = 0; r < 16; r++) {
        int idx = tid + r * 256, d = idx >> 6, e = idx & 63;
        dst[(size_t)d * E_ + e0 + e] = rna(tt[e][d]);
    }
}

// g_wpT[n][k] = rna(wp[k][n])
__global__ __launch_bounds__(256)
void tr_wp(const float* __restrict__ wp)
{
    __shared__ float tt[64][65];
    const int k0 = blockIdx.x * 64, n0 = blockIdx.y * 64;
    const int tid = threadIdx.x;
    #pragma unroll
    for (int r = 0; r < 16; r++) {
        int idx = tid + r * 256, k = idx >> 6, n = idx & 63;
        tt[k][n] = wp[(size_t)(k0 + k) * E_ + n0 + n];
    }
    __syncthreads();
    #pragma unroll
    for (int r = 0; r < 16; r++) {
        int idx = tid + r * 256, n = idx >> 6, k = idx & 63;
        g_wpT[(size_t)(n0 + n) * NH + k0 + k] = rna(tt[k][n]);
    }
}

// ======================= GEMM core (tf32 mma.sync) =========================
// C[128,128] block tile, K=512, chunks of 32, cp.async double-buffered.
// 256 threads = 8 warps in 2(m) x 4(n); warp tile 64x32; 4x4 m16n8 tiles.
#define GEMM_SMEM (4 * 18432)   // 2 stages x (A,B) x 128x36 floats

__device__ __forceinline__ void gemm_issue(uint32_t sb, int st, int c,
                                           const float* __restrict__ Ag,
                                           const float* __restrict__ Bg,
                                           int m0, int n0)
{
    const int tid = threadIdx.x;
    uint32_t as_ = sb + (uint32_t)(st * 2 + 0) * 18432;
    uint32_t bs_ = sb + (uint32_t)(st * 2 + 1) * 18432;
    #pragma unroll
    for (int i = 0; i < 4; i++) {
        int idx = tid + i * 256, row = idx >> 3, f4 = idx & 7;
        CP16(as_ + (uint32_t)(row * 36 + f4 * 4) * 4,
             Ag + (size_t)(m0 + row) * 512 + c * 32 + f4 * 4);
        CP16(bs_ + (uint32_t)(row * 36 + f4 * 4) * 4,
             Bg + (size_t)(n0 + row) * 512 + c * 32 + f4 * 4);
    }
    CPCOMMIT();
}

__device__ __forceinline__ void gemm_core(const float* __restrict__ Ag,
                                          const float* __restrict__ Bg,
                                          float acc[4][4][4])
{
    extern __shared__ char gsm[];
    const uint32_t sb = smem_u32(gsm);
    const int tid = threadIdx.x;
    const int m0 = blockIdx.x * 128, n0 = blockIdx.y * 128;
    const int wid = tid >> 5, wm = wid >> 2, wn = wid & 3;
    const int lane = tid & 31, g = lane >> 2, t = lane & 3;

    gemm_issue(sb, 0, 0, Ag, Bg, m0, n0);

    for (int c = 0; c < 16; c++) {
        CPWAIT0();
        __syncthreads();
        if (c < 15) gemm_issue(sb, (c + 1) & 1, c + 1, Ag, Bg, m0, n0);

        const uint32_t* As = (const uint32_t*)(gsm + ((c & 1) * 2 + 0) * 18432);
        const uint32_t* Bs = (const uint32_t*)(gsm + ((c & 1) * 2 + 1) * 18432);
        #pragma unroll
        for (int ks = 0; ks < 4; ks++) {
            uint32_t a[4][4], bb[4][2];
            #pragma unroll
            for (int mt = 0; mt < 4; mt++) {
                int r = wm * 64 + mt * 16;
                a[mt][0] = As[(r + g)     * 36 + ks * 8 + t];
                a[mt][1] = As[(r + g + 8) * 36 + ks * 8 + t];
                a[mt][2] = As[(r + g)     * 36 + ks * 8 + t + 4];
                a[mt][3] = As[(r + g + 8) * 36 + ks * 8 + t + 4];
            }
            #pragma unroll
            for (int nt = 0; nt < 4; nt++) {
                int rn = wn * 32 + nt * 8;
                bb[nt][0] = Bs[(rn + g) * 36 + ks * 8 + t];
                bb[nt][1] = Bs[(rn + g) * 36 + ks * 8 + t + 4];
            }
            #pragma unroll
            for (int mt = 0; mt < 4; mt++)
                #pragma unroll
                for (int nt = 0; nt < 4; nt++)
                    mma8(acc[mt][nt], a[mt], bb[nt]);
        }
    }
}

// qkv: C[8192,1536] = g_xr @ g_wqkv^T(K-major); scatter to g_q/g_k/g_v
__global__ __launch_bounds__(256)
void qkv_gemm()
{
    float acc[4][4][4] = {};
    gemm_core(g_xr, g_wqkv, acc);

    const int tid = threadIdx.x;
    const int wid = tid >> 5, wm = wid >> 2, wn = wid & 3;
    const int lane = tid & 31, g = lane >> 2, t = lane & 3;
    const int m0 = blockIdx.x * 128, n0 = blockIdx.y * 128;

    #pragma unroll
    for (int nt = 0; nt < 4; nt++) {
        int nb = n0 + wn * 32 + nt * 8;
        int w = nb >> 9, h = (nb >> 6) & 7, d = (nb & 63) + 2 * t;
        float* dst = (w == 0 ? g_q : (w == 1 ? g_k : g_v));
        #pragma unroll
        for (int mt = 0; mt < 4; mt++) {
            int m = m0 + wm * 64 + mt * 16 + g;
            int b = m >> 11, tt = m & 2047;
            size_t base = ((size_t)(b * H_ + h) * T_ + tt) * HS_ + d;
            float2 v0 = { rna(acc[mt][nt][0]), rna(acc[mt][nt][1]) };
            float2 v1 = { rna(acc[mt][nt][2]), rna(acc[mt][nt][3]) };
            *(float2*)(dst + base)            = v0;
            *(float2*)(dst + base + 8 * HS_)  = v1;
        }
    }
}

// proj: out[8192,512] = g_o @ wp (via K-major g_wpT)
__global__ __launch_bounds__(256)
void proj_gemm(float* __restrict__ out)
{
    float acc[4][4][4] = {};
    gemm_core(g_o, g_wpT, acc);

    const int tid = threadIdx.x;
    const int wid = tid >> 5, wm = wid >> 2, wn = wid & 3;
    const int lane = tid & 31, g = lane >> 2, t = lane & 3;
    const int m0 = blockIdx.x * 128, n0 = blockIdx.y * 128;

    #pragma unroll
    for (int nt = 0; nt < 4; nt++) {
        int n = n0 + wn * 32 + nt * 8 + 2 * t;
        #pragma unroll
        for (int mt = 0; mt < 4; mt++) {
            int m = m0 + wm * 64 + mt * 16 + g;
            float2 v0 = { acc[mt][nt][0], acc[mt][nt][1] };
            float2 v1 = { acc[mt][nt][2], acc[mt][nt][3] };
            *(float2*)(out + (size_t)m * E_ + n)       = v0;
            *(float2*)(out + (size_t)(m + 8) * E_ + n) = v1;
        }
    }
}

// ======================= flash attention (tf32 mma.sync) ===================
// Block: (b, h, 64-query tile), 4 warps. Warp owns 16 query rows x 64 cols.
#define ATT_SMEM (3 * 64 * 68 * 4)   // Ks, Vs, Ps : 52224 B

__global__ __launch_bounds__(128)
void attn_tc()
{
    extern __shared__ float sm[];
    float (*Ks)[68] = (float(*)[68])sm;
    float (*Vs)[68] = (float(*)[68])(sm + 64 * 68);
    float (*Ps)[68] = (float(*)[68])(sm + 2 * 64 * 68);

    const int b = blockIdx.z, h = blockIdx.y;
    const int qt = (T_ / 64) - 1 - blockIdx.x;      // heavy tiles first
    const int m0 = qt * 64;
    const int tid = threadIdx.x, wid = tid >> 5, lane = tid & 31;
    const int g = lane >> 2, t = lane & 3;
    const int mrow = wid * 16;

    const float* qp = g_q + (size_t)(b * H_ + h) * T_ * HS_;
    const float* kp = g_k + (size_t)(b * H_ + h) * T_ * HS_;
    const float* vp = g_v + (size_t)(b * H_ + h) * T_ * HS_;

    // stage this warp's Q rows, extract persistent A fragments
    {
        const float* qw = qp + (size_t)(m0 + mrow) * HS_;
        #pragma unroll
        for (int r = 0; r < 8; r++) {
            int idx = lane + r * 32, row = idx >> 4, f4 = idx & 15;
            *(float4*)&Ps[mrow + row][f4 * 4] =
                *(const float4*)(qw + (size_t)row * HS_ + f4 * 4);
        }
        __syncwarp();
    }
    uint32_t q[8][4];
    #pragma unroll
    for (int ks = 0; ks < 8; ks++) {
        q[ks][0] = __float_as_uint(Ps[mrow + g    ][ks * 8 + t]);
        q[ks][1] = __float_as_uint(Ps[mrow + g + 8][ks * 8 + t]);
        q[ks][2] = __float_as_uint(Ps[mrow + g    ][ks * 8 + t + 4]);
        q[ks][3] = __float_as_uint(Ps[mrow + g + 8][ks * 8 + t + 4]);
    }

    float o[8][4] = {};
    float mr0 = -1e30f, mr1 = -1e30f, l0 = 0.0f, l1 = 0.0f;
    const int r0 = m0 + mrow + g, r1 = r0 + 8;

    for (int kt = 0; kt <= qt; kt++) {
        const int n0 = kt * 64;
        __syncthreads();
        #pragma unroll
        for (int r = 0; r < 8; r++) {
            int idx = tid + r * 128, row = idx >> 4, f4 = idx & 15;
            *(float4*)&Ks[row][f4 * 4] =
                *(const float4*)(kp + (size_t)(n0 + row) * HS_ + f4 * 4);
            *(float4*)&Vs[row][f4 * 4] =
                *(const float4*)(vp + (size_t)(n0 + row) * HS_ + f4 * 4);
        }
        __syncthreads();

        // S = Q K^T
        float s[8][4] = {};
        #pragma unroll
        for (int ks = 0; ks < 8; ks++) {
            #pragma unroll
            for (int nt = 0; nt < 8; nt++) {
                uint32_t bk[2];
                bk[0] = __float_as_uint(Ks[nt * 8 + g][ks * 8 + t]);
                bk[1] = __float_as_uint(Ks[nt * 8 + g][ks * 8 + t + 4]);
                mma8(s[nt], q[ks], bk);
            }
        }

        const float sc = 0.125f;   // 1/sqrt(64)
        #pragma unroll
        for (int nt = 0; nt < 8; nt++) {
            s[nt][0] *= sc; s[nt][1] *= sc; s[nt][2] *= sc; s[nt][3] *= sc;
        }
        if (kt == qt) {
            #pragma unroll
            for (int nt = 0; nt < 8; nt++) {
                int c0 = n0 + nt * 8 + 2 * t, c1 = c0 + 1;
                if (c0 > r0) s[nt][0] = -1e30f;
                if (c1 > r0) s[nt][1] = -1e30f;
                if (c0 > r1) s[nt][2] = -1e30f;
                if (c1 > r1) s[nt][3] = -1e30f;
            }
        }

        // online softmax (rows r0, r1); stats shared across 4-lane groups
        float mx0 = -1e30f, mx1 = -1e30f;
        #pragma unroll
        for (int nt = 0; nt < 8; nt++) {
            mx0 = fmaxf(mx0, fmaxf(s[nt][0], s[nt][1]));
            mx1 = fmaxf(mx1, fmaxf(s[nt][2], s[nt][3]));
        }
        mx0 = fmaxf(mx0, __shfl_xor_sync(0xffffffffu, mx0, 1));
        mx0 = fmaxf(mx0, __shfl_xor_sync(0xffffffffu, mx0, 2));
        mx1 = fmaxf(mx1, __shfl_xor_sync(0xffffffffu, mx1, 1));
        mx1 = fmaxf(mx1, __shfl_xor_sync(0xffffffffu, mx1, 2));
        float mn0 = fmaxf(mr0, mx0), mn1 = fmaxf(mr1, mx1);
        float al0 = __expf(mr0 - mn0), al1 = __expf(mr1 - mn1);
        mr0 = mn0; mr1 = mn1;

        float su0 = 0.0f, su1 = 0.0f;
        #pragma unroll
        for (int nt = 0; nt < 8; nt++) {
            s[nt][0] = __expf(s[nt][0] - mn0);
            s[nt][1] = __expf(s[nt][1] - mn0);
            s[nt][2] = __expf(s[nt][2] - mn1);
            s[nt][3] = __expf(s[nt][3] - mn1);
            su0 += s[nt][0] + s[nt][1];
            su1 += s[nt][2] + s[nt][3];
        }
        su0 += __shfl_xor_sync(0xffffffffu, su0, 1);
        su0 += __shfl_xor_sync(0xffffffffu, su0, 2);
        su1 += __shfl_xor_sync(0xffffffffu, su1, 1);
        su1 += __shfl_xor_sync(0xffffffffu, su1, 2);
        l0 = l0 * al0 + su0;
        l1 = l1 * al1 + su1;

        #pragma unroll
        for (int nt = 0; nt < 8; nt++) {
            o[nt][0] *= al0; o[nt][1] *= al0; o[nt][2] *= al1; o[nt][3] *= al1;
        }

        // stage P (tf32-rounded) into this warp's Ps slice
        __syncwarp();
        #pragma unroll
        for (int nt = 0; nt < 8; nt++) {
            float2 p0 = { rna(s[nt][0]), rna(s[nt][1]) };
            float2 p1 = { rna(s[nt][2]), rna(s[nt][3]) };
            *(float2*)&Ps[mrow + g    ][nt * 8 + 2 * t] = p0;
            *(float2*)&Ps[mrow + g + 8][nt * 8 + 2 * t] = p1;
        }
        __syncwarp();

        // O += P V
        #pragma unroll
        for (int ks = 0; ks < 8; ks++) {
            uint32_t pa[4];
            pa[0] = __float_as_uint(Ps[mrow + g    ][ks * 8 + t]);
            pa[1] = __float_as_uint(Ps[mrow + g + 8][ks * 8 + t]);
            pa[2] = __float_as_uint(Ps[mrow + g    ][ks * 8 + t + 4]);
            pa[3] = __float_as_uint(Ps[mrow + g + 8][ks * 8 + t + 4]);
            #pragma unroll
            for (int nt = 0; nt < 8; nt++) {
                uint32_t bv[2];
                bv[0] = __float_as_uint(Vs[ks * 8 + t    ][nt * 8 + g]);
                bv[1] = __float_as_uint(Vs[ks * 8 + t + 4][nt * 8 + g]);
                mma8(o[nt], pa, bv);
            }
        }
    }

    // epilogue: normalize, round for the proj MMA, write [B,T,H*HS]
    float i0 = 1.0f / l0, i1 = 1.0f / l1;
    float* op = g_o + ((size_t)b * T_ + m0 + mrow) * NH + h * HS_;
    #pragma unroll
    for (int nt = 0; nt < 8; nt++) {
        int c = nt * 8 + 2 * t;
        float2 v0 = { rna(o[nt][0] * i0), rna(o[nt][1] * i0) };
        float2 v1 = { rna(o[nt][2] * i1), rna(o[nt][3] * i1) };
        *(float2*)&op[(size_t)g * NH + c]       = v0;
        *(float2*)&op[(size_t)(g + 8) * NH + c] = v1;
    }
}

// ---------------------------------------------------------------------------
extern "C" void kernel_launch(void* const* d_in, const int* in_sizes, int n_in,
                              void* d_out, int out_size)
{
    const float* x  = (const float*)d_in[0];
    const float* wq = (const float*)d_in[1];
    const float* wk = (const float*)d_in[2];
    const float* wv = (const float*)d_in[3];
    const float* wp = (const float*)d_in[4];
    float* out = (float*)d_out;

    cudaFuncSetAttribute(qkv_gemm,  cudaFuncAttributeMaxDynamicSharedMemorySize, GEMM_SMEM);
    cudaFuncSetAttribute(proj_gemm, cudaFuncAttributeMaxDynamicSharedMemorySize, GEMM_SMEM);
    cudaFuncSetAttribute(attn_tc,   cudaFuncAttributeMaxDynamicSharedMemorySize, ATT_SMEM);

    round_x<<<(B_ * T_ * E_) / 1024, 256>>>(x);
    tr_wqkv<<<dim3(E_ / 64, H_, 3), 256>>>(wq, wk, wv);
    tr_wp<<<dim3(E_ / 64, E_ / 64), 256>>>(wp);
    qkv_gemm<<<dim3((B_ * T_) / 128, (3 * NH) / 128), 256, GEMM_SMEM>>>();
    attn_tc<<<dim3(T_ / 64, H_, B_), 128, ATT_SMEM>>>();
    proj_gemm<<<dim3((B_ * T_) / 128, E_ / 128), 256, GEMM_SMEM>>>(out);
}

// round 5
// speedup vs baseline: 3.5207x; 1.1750x over previous
#include <cuda_runtime.h>
#include <cstdint>

#define B_  4
#define T_  2048
#define E_  512
#define H_  8
#define HS_ 64
#define NH  (H_ * HS_)   // 512

// ---------------- scratch (device globals; no allocation allowed) ----------
__device__ float g_q[(size_t)B_ * H_ * T_ * HS_];   // [B,H,T,HS], tf32-rounded
__device__ float g_k[(size_t)B_ * H_ * T_ * HS_];
__device__ float g_v[(size_t)B_ * H_ * T_ * HS_];
__device__ float g_o[(size_t)B_ * T_ * NH];         // [B,T,H*HS], tf32-rounded
__device__ float g_xr[(size_t)B_ * T_ * E_];        // tf32-rounded x
__device__ float g_wqkv[3 * NH * E_];               // K-major [w*512+h*64+d][e]
__device__ float g_wpT[E_ * NH];                    // K-major [n][k]

// ======================= helpers ===========================================
__device__ __forceinline__ uint32_t smem_u32(const void* p) {
    uint32_t a;
    asm("{ .reg .u64 t; cvta.to.shared.u64 t, %1; cvt.u32.u64 %0, t; }"
        : "=r"(a) : "l"(p));
    return a;
}
__device__ __forceinline__ float rna(float x) {
    uint32_t r;
    asm("cvt.rna.tf32.f32 %0, %1;" : "=r"(r) : "f"(x));
    return __uint_as_float(r);
}
__device__ __forceinline__ void mma8(float d[4], const uint32_t a[4],
                                     const uint32_t b[2]) {
    asm volatile(
        "mma.sync.aligned.m16n8k8.row.col.f32.tf32.tf32.f32 "
        "{%0,%1,%2,%3},{%4,%5,%6,%7},{%8,%9},{%0,%1,%2,%3};"
        : "+f"(d[0]), "+f"(d[1]), "+f"(d[2]), "+f"(d[3])
        : "r"(a[0]), "r"(a[1]), "r"(a[2]), "r"(a[3]), "r"(b[0]), "r"(b[1]));
}
#define CP16(ds, sp)  asm volatile("cp.async.cg.shared.global [%0], [%1], 16;" :: "r"(ds), "l"(sp))
#define CPCOMMIT()    asm volatile("cp.async.commit_group;" ::: "memory")
#define CPWAIT0()     asm volatile("cp.async.wait_group 0;" ::: "memory")

// ======================= prep kernels ======================================
__global__ __launch_bounds__(256)
void round_x(const float* __restrict__ x)
{
    size_t i = ((size_t)blockIdx.x * 256 + threadIdx.x) * 4;
    float4 v = *(const float4*)(x + i);
    v.x = rna(v.x); v.y = rna(v.y); v.z = rna(v.z); v.w = rna(v.w);
    *(float4*)(g_xr + i) = v;
}

__global__ __launch_bounds__(256)
void tr_wqkv(const float* __restrict__ wq, const float* __restrict__ wk,
             const float* __restrict__ wv)
{
    __shared__ float tt[64][65];
    const int w = blockIdx.z, h = blockIdx.y, e0 = blockIdx.x * 64;
    const float* src = (w == 0 ? wq : (w == 1 ? wk : wv)) + (size_t)h * E_ * HS_;
    const int tid = threadIdx.x;
    #pragma unroll
    for (int r = 0; r < 16; r++) {
        int idx = tid + r * 256, e = idx >> 6, d = idx & 63;
        tt[e][d] = src[(size_t)(e0 + e) * HS_ + d];
    }
    __syncthreads();
    float* dst = g_wqkv + (size_t)(w * 512 + h * 64) * E_;
    #pragma unroll
    for (int r = 0; r < 16; r++) {
        int idx = tid + r * 256, d = idx >> 6, e = idx & 63;
        dst[(size_t)d * E_ + e0 + e] = rna(tt[e][d]);
    }
}

__global__ __launch_bounds__(256)
void tr_wp(const float* __restrict__ wp)
{
    __shared__ float tt[64][65];
    const int k0 = blockIdx.x * 64, n0 = blockIdx.y * 64;
    const int tid = threadIdx.x;
    #pragma unroll
    for (int r = 0; r < 16; r++) {
        int idx = tid + r * 256, k = idx >> 6, n = idx & 63;
        tt[k][n] = wp[(size_t)(k0 + k) * E_ + n0 + n];
    }
    __syncthreads();
    #pragma unroll
    for (int r = 0; r < 16; r++) {
        int idx = tid + r * 256, n = idx >> 6, k = idx & 63;
        g_wpT[(size_t)(n0 + n) * NH + k0 + k] = rna(tt[k][n]);
    }
}

// ======================= GEMM core (tf32 mma.sync) =========================
// 128 threads = 4 warps in 2x2. Block tile 128x128, warp tile 64x64.
// K chunks of 32, cp.async 2-stage. Register double-buffered fragments.
#define GEMM_SMEM (4 * 18432)   // 2 stages x (A,B) x 128x36 floats

__device__ __forceinline__ void gemm_issue(uint32_t sb, int st, int c,
                                           const float* __restrict__ Ag,
                                           const float* __restrict__ Bg,
                                           int m0, int n0)
{
    const int tid = threadIdx.x;
    uint32_t as_ = sb + (uint32_t)(st * 2 + 0) * 18432;
    uint32_t bs_ = sb + (uint32_t)(st * 2 + 1) * 18432;
    #pragma unroll
    for (int i = 0; i < 8; i++) {
        int idx = tid + i * 128, row = idx >> 3, f4 = idx & 7;
        CP16(as_ + (uint32_t)(row * 36 + f4 * 4) * 4,
             Ag + (size_t)(m0 + row) * 512 + c * 32 + f4 * 4);
        CP16(bs_ + (uint32_t)(row * 36 + f4 * 4) * 4,
             Bg + (size_t)(n0 + row) * 512 + c * 32 + f4 * 4);
    }
    CPCOMMIT();
}

__device__ __forceinline__ void gemm_core(const float* __restrict__ Ag,
                                          const float* __restrict__ Bg,
                                          float acc[4][8][4])
{
    extern __shared__ char gsm[];
    const uint32_t sb = smem_u32(gsm);
    const int tid = threadIdx.x;
    const int m0 = blockIdx.x * 128, n0 = blockIdx.y * 128;
    const int wid = tid >> 5, wm = wid >> 1, wn = wid & 1;
    const int lane = tid & 31, g = lane >> 2, t = lane & 3;

    gemm_issue(sb, 0, 0, Ag, Bg, m0, n0);

    for (int c = 0; c < 16; c++) {
        CPWAIT0();
        __syncthreads();
        if (c < 15) gemm_issue(sb, (c + 1) & 1, c + 1, Ag, Bg, m0, n0);

        const uint32_t* As = (const uint32_t*)(gsm + ((c & 1) * 2 + 0) * 18432);
        const uint32_t* Bs = (const uint32_t*)(gsm + ((c & 1) * 2 + 1) * 18432);

        uint32_t a[2][4][4], bb[2][8][2];
        auto ldf = [&](int ks, int sl) {
            #pragma unroll
            for (int mt = 0; mt < 4; mt++) {
                int r = wm * 64 + mt * 16;
                a[sl][mt][0] = As[(r + g)     * 36 + ks * 8 + t];
                a[sl][mt][1] = As[(r + g + 8) * 36 + ks * 8 + t];
                a[sl][mt][2] = As[(r + g)     * 36 + ks * 8 + t + 4];
                a[sl][mt][3] = As[(r + g + 8) * 36 + ks * 8 + t + 4];
            }
            #pragma unroll
            for (int nt = 0; nt < 8; nt++) {
                int rn = wn * 64 + nt * 8;
                bb[sl][nt][0] = Bs[(rn + g) * 36 + ks * 8 + t];
                bb[sl][nt][1] = Bs[(rn + g) * 36 + ks * 8 + t + 4];
            }
        };
        ldf(0, 0);
        #pragma unroll
        for (int ks = 0; ks < 4; ks++) {
            int cur = ks & 1;
            if (ks < 3) ldf(ks + 1, cur ^ 1);
            #pragma unroll
            for (int mt = 0; mt < 4; mt++)
                #pragma unroll
                for (int nt = 0; nt < 8; nt++)
                    mma8(acc[mt][nt], a[cur][mt], bb[cur][nt]);
        }
    }
}

// qkv: C[8192,1536] = g_xr @ g_wqkv^T(K-major); scatter to g_q/g_k/g_v
__global__ __launch_bounds__(128)
void qkv_gemm()
{
    float acc[4][8][4] = {};
    gemm_core(g_xr, g_wqkv, acc);

    const int tid = threadIdx.x;
    const int wid = tid >> 5, wm = wid >> 1, wn = wid & 1;
    const int lane = tid & 31, g = lane >> 2, t = lane & 3;
    const int m0 = blockIdx.x * 128, n0 = blockIdx.y * 128;

    #pragma unroll
    for (int nt = 0; nt < 8; nt++) {
        int nb = n0 + wn * 64 + nt * 8;
        int w = nb >> 9, h = (nb >> 6) & 7, d = (nb & 63) + 2 * t;
        float* dst = (w == 0 ? g_q : (w == 1 ? g_k : g_v));
        #pragma unroll
        for (int mt = 0; mt < 4; mt++) {
            int m = m0 + wm * 64 + mt * 16 + g;
            int b = m >> 11, tt = m & 2047;
            size_t base = ((size_t)(b * H_ + h) * T_ + tt) * HS_ + d;
            float2 v0 = { rna(acc[mt][nt][0]), rna(acc[mt][nt][1]) };
            float2 v1 = { rna(acc[mt][nt][2]), rna(acc[mt][nt][3]) };
            *(float2*)(dst + base)           = v0;
            *(float2*)(dst + base + 8 * HS_) = v1;
        }
    }
}

// proj: out[8192,512] = g_o @ wp (via K-major g_wpT)
__global__ __launch_bounds__(128)
void proj_gemm(float* __restrict__ out)
{
    float acc[4][8][4] = {};
    gemm_core(g_o, g_wpT, acc);

    const int tid = threadIdx.x;
    const int wid = tid >> 5, wm = wid >> 1, wn = wid & 1;
    const int lane = tid & 31, g = lane >> 2, t = lane & 3;
    const int m0 = blockIdx.x * 128, n0 = blockIdx.y * 128;

    #pragma unroll
    for (int nt = 0; nt < 8; nt++) {
        int n = n0 + wn * 64 + nt * 8 + 2 * t;
        #pragma unroll
        for (int mt = 0; mt < 4; mt++) {
            int m = m0 + wm * 64 + mt * 16 + g;
            float2 v0 = { acc[mt][nt][0], acc[mt][nt][1] };
            float2 v1 = { acc[mt][nt][2], acc[mt][nt][3] };
            *(float2*)(out + (size_t)m * E_ + n)       = v0;
            *(float2*)(out + (size_t)(m + 8) * E_ + n) = v1;
        }
    }
}

// ======================= flash attention (tf32 mma.sync) ===================
// 128 threads = 4 warps. Q tile 128 rows, warp = 32 rows (2 m16 sub-tiles).
// K/V 64-key tiles, cp.async double-buffered. smem 106496 B.
#define ATT_KOFF  0                      // K: [2][64][68]
#define ATT_VOFF  (2 * 64 * 68)          // V: [2][64][72]
#define ATT_POFF  (ATT_VOFF + 2 * 64 * 72)   // Ps: [128][68]
#define ATT_SMEM  ((ATT_POFF + 128 * 68) * 4)

__device__ __forceinline__ void attn_stage(uint32_t sb,
                                           const float* __restrict__ kp,
                                           const float* __restrict__ vp,
                                           int n0, int buf)
{
    const int tid = threadIdx.x;
    uint32_t kb = sb + (uint32_t)(ATT_KOFF + buf * 64 * 68) * 4;
    uint32_t vb = sb + (uint32_t)(ATT_VOFF + buf * 64 * 72) * 4;
    #pragma unroll
    for (int i = 0; i < 8; i++) {
        int idx = tid + i * 128, row = idx >> 4, f4 = idx & 15;
        CP16(kb + (uint32_t)(row * 68 + f4 * 4) * 4,
             kp + (size_t)(n0 + row) * HS_ + f4 * 4);
        CP16(vb + (uint32_t)(row * 72 + f4 * 4) * 4,
             vp + (size_t)(n0 + row) * HS_ + f4 * 4);
    }
    CPCOMMIT();
}

__global__ __launch_bounds__(128)
void attn_tc()
{
    extern __shared__ float sm[];
    float (*Kbuf)[68] = (float(*)[68])(sm + ATT_KOFF);
    float (*Vbuf)[72] = (float(*)[72])(sm + ATT_VOFF);
    float (*Ps)[68]   = (float(*)[68])(sm + ATT_POFF);
    const uint32_t sb = smem_u32(sm);

    const int b = blockIdx.z, h = blockIdx.y;
    const int qt = (T_ / 128) - 1 - blockIdx.x;   // heavy tiles first
    const int m0 = qt * 128;
    const int tid = threadIdx.x, wid = tid >> 5, lane = tid & 31;
    const int g = lane >> 2, t = lane & 3;
    const int mrow = wid * 32;
    const int ktmax = m0 / 64 + 2;

    const float* qp = g_q + (size_t)(b * H_ + h) * T_ * HS_;
    const float* kp = g_k + (size_t)(b * H_ + h) * T_ * HS_;
    const float* vp = g_v + (size_t)(b * H_ + h) * T_ * HS_;

    attn_stage(sb, kp, vp, 0, 0);

    // stage this warp's 32 Q rows into its Ps slice, extract A fragments
    {
        const float* qw = qp + (size_t)(m0 + mrow) * HS_;
        #pragma unroll
        for (int r = 0; r < 16; r++) {
            int idx = lane + r * 32, row = idx >> 4, f4 = idx & 15;
            *(float4*)&Ps[mrow + row][f4 * 4] =
                *(const float4*)(qw + (size_t)row * HS_ + f4 * 4);
        }
        __syncwarp();
    }
    uint32_t q[2][8][4];
    #pragma unroll
    for (int ms = 0; ms < 2; ms++) {
        int r = mrow + ms * 16;
        #pragma unroll
        for (int ks = 0; ks < 8; ks++) {
            q[ms][ks][0] = __float_as_uint(Ps[r + g    ][ks * 8 + t]);
            q[ms][ks][1] = __float_as_uint(Ps[r + g + 8][ks * 8 + t]);
            q[ms][ks][2] = __float_as_uint(Ps[r + g    ][ks * 8 + t + 4]);
            q[ms][ks][3] = __float_as_uint(Ps[r + g + 8][ks * 8 + t + 4]);
        }
    }

    float o[2][8][4] = {};
    float mrA[2] = {-1e30f, -1e30f}, mrB[2] = {-1e30f, -1e30f};
    float lA[2] = {}, lB[2] = {};

    for (int kt = 0; kt < ktmax; kt++) {
        CPWAIT0();
        __syncthreads();
        if (kt + 1 < ktmax) attn_stage(sb, kp, vp, (kt + 1) * 64, (kt + 1) & 1);

        const int n0 = kt * 64;
        const int buf = kt & 1;
        if (n0 <= m0 + mrow + 31) {
            const float (*Ks)[68] = Kbuf + buf * 64;
            const float (*Vs)[72] = Vbuf + buf * 64;

            // S = Q K^T (B fragments shared by both m-subtiles)
            float s[2][8][4] = {};
            #pragma unroll
            for (int ks = 0; ks < 8; ks++) {
                #pragma unroll
                for (int nt = 0; nt < 8; nt++) {
                    uint32_t bk[2];
                    bk[0] = __float_as_uint(Ks[nt * 8 + g][ks * 8 + t]);
                    bk[1] = __float_as_uint(Ks[nt * 8 + g][ks * 8 + t + 4]);
                    mma8(s[0][nt], q[0][ks], bk);
                    mma8(s[1][nt], q[1][ks], bk);
                }
            }

            const float sc = 0.125f;   // 1/sqrt(64)
            #pragma unroll
            for (int ms = 0; ms < 2; ms++)
                #pragma unroll
                for (int nt = 0; nt < 8; nt++) {
                    s[ms][nt][0] *= sc; s[ms][nt][1] *= sc;
                    s[ms][nt][2] *= sc; s[ms][nt][3] *= sc;
                }
            if (n0 + 63 > m0 + mrow) {   // diagonal region: causal mask
                #pragma unroll
                for (int ms = 0; ms < 2; ms++) {
                    int rA = m0 + mrow + ms * 16 + g, rB = rA + 8;
                    #pragma unroll
                    for (int nt = 0; nt < 8; nt++) {
                        int c0 = n0 + nt * 8 + 2 * t, c1 = c0 + 1;
                        if (c0 > rA) s[ms][nt][0] = -1e30f;
                        if (c1 > rA) s[ms][nt][1] = -1e30f;
                        if (c0 > rB) s[ms][nt][2] = -1e30f;
                        if (c1 > rB) s[ms][nt][3] = -1e30f;
                    }
                }
            }

            // online softmax per m-subtile
            #pragma unroll
            for (int ms = 0; ms < 2; ms++) {
                float mx0 = -1e30f, mx1 = -1e30f;
                #pragma unroll
                for (int nt = 0; nt < 8; nt++) {
                    mx0 = fmaxf(mx0, fmaxf(s[ms][nt][0], s[ms][nt][1]));
                    mx1 = fmaxf(mx1, fmaxf(s[ms][nt][2], s[ms][nt][3]));
                }
                mx0 = fmaxf(mx0, __shfl_xor_sync(0xffffffffu, mx0, 1));
                mx0 = fmaxf(mx0, __shfl_xor_sync(0xffffffffu, mx0, 2));
                mx1 = fmaxf(mx1, __shfl_xor_sync(0xffffffffu, mx1, 1));
                mx1 = fmaxf(mx1, __shfl_xor_sync(0xffffffffu, mx1, 2));
                float mn0 = fmaxf(mrA[ms], mx0), mn1 = fmaxf(mrB[ms], mx1);
                float al0 = __expf(mrA[ms] - mn0), al1 = __expf(mrB[ms] - mn1);
                mrA[ms] = mn0; mrB[ms] = mn1;

                float su0 = 0.0f, su1 = 0.0f;
                #pragma unroll
                for (int nt = 0; nt < 8; nt++) {
                    s[ms][nt][0] = __expf(s[ms][nt][0] - mn0);
                    s[ms][nt][1] = __expf(s[ms][nt][1] - mn0);
                    s[ms][nt][2] = __expf(s[ms][nt][2] - mn1);
                    s[ms][nt][3] = __expf(s[ms][nt][3] - mn1);
                    su0 += s[ms][nt][0] + s[ms][nt][1];
                    su1 += s[ms][nt][2] + s[ms][nt][3];
                }
                su0 += __shfl_xor_sync(0xffffffffu, su0, 1);
                su0 += __shfl_xor_sync(0xffffffffu, su0, 2);
                su1 += __shfl_xor_sync(0xffffffffu, su1, 1);
                su1 += __shfl_xor_sync(0xffffffffu, su1, 2);
                lA[ms] = lA[ms] * al0 + su0;
                lB[ms] = lB[ms] * al1 + su1;

                #pragma unroll
                for (int nt = 0; nt < 8; nt++) {
                    o[ms][nt][0] *= al0; o[ms][nt][1] *= al0;
                    o[ms][nt][2] *= al1; o[ms][nt][3] *= al1;
                }
            }

            // stage P (tf32-rounded) into this warp's Ps slice
            __syncwarp();
            #pragma unroll
            for (int ms = 0; ms < 2; ms++) {
                int r = mrow + ms * 16;
                #pragma unroll
                for (int nt = 0; nt < 8; nt++) {
                    float2 p0 = { rna(s[ms][nt][0]), rna(s[ms][nt][1]) };
                    float2 p1 = { rna(s[ms][nt][2]), rna(s[ms][nt][3]) };
                    *(float2*)&Ps[r + g    ][nt * 8 + 2 * t] = p0;
                    *(float2*)&Ps[r + g + 8][nt * 8 + 2 * t] = p1;
                }
            }
            __syncwarp();

            // O += P V (V fragments shared by both m-subtiles)
            #pragma unroll
            for (int ks = 0; ks < 8; ks++) {
                uint32_t pa[2][4];
                #pragma unroll
                for (int ms = 0; ms < 2; ms++) {
                    int r = mrow + ms * 16;
                    pa[ms][0] = __float_as_uint(Ps[r + g    ][ks * 8 + t]);
                    pa[ms][1] = __float_as_uint(Ps[r + g + 8][ks * 8 + t]);
                    pa[ms][2] = __float_as_uint(Ps[r + g    ][ks * 8 + t + 4]);
                    pa[ms][3] = __float_as_uint(Ps[r + g + 8][ks * 8 + t + 4]);
                }
                #pragma unroll
                for (int nt = 0; nt < 8; nt++) {
                    uint32_t bv[2];
                    bv[0] = __float_as_uint(Vs[ks * 8 + t    ][nt * 8 + g]);
                    bv[1] = __float_as_uint(Vs[ks * 8 + t + 4][nt * 8 + g]);
                    mma8(o[0][nt], pa[0], bv);
                    mma8(o[1][nt], pa[1], bv);
                }
            }
        }
    }

    // epilogue: normalize, round for the proj MMA, write [B,T,H*HS]
    float* op = g_o + ((size_t)b * T_ + m0 + mrow) * NH + h * HS_;
    #pragma unroll
    for (int ms = 0; ms < 2; ms++) {
        float iA = 1.0f / lA[ms], iB = 1.0f / lB[ms];
        int rr = ms * 16 + g;
        #pragma unroll
        for (int nt = 0; nt < 8; nt++) {
            int c = nt * 8 + 2 * t;
            float2 v0 = { rna(o[ms][nt][0] * iA), rna(o[ms][nt][1] * iA) };
            float2 v1 = { rna(o[ms][nt][2] * iB), rna(o[ms][nt][3] * iB) };
            *(float2*)&op[(size_t)rr * NH + c]       = v0;
            *(float2*)&op[(size_t)(rr + 8) * NH + c] = v1;
        }
    }
}

// ---------------------------------------------------------------------------
extern "C" void kernel_launch(void* const* d_in, const int* in_sizes, int n_in,
                              void* d_out, int out_size)
{
    const float* x  = (const float*)d_in[0];
    const float* wq = (const float*)d_in[1];
    const float* wk = (const float*)d_in[2];
    const float* wv = (const float*)d_in[3];
    const float* wp = (const float*)d_in[4];
    float* out = (float*)d_out;

    cudaFuncSetAttribute(qkv_gemm,  cudaFuncAttributeMaxDynamicSharedMemorySize, GEMM_SMEM);
    cudaFuncSetAttribute(proj_gemm, cudaFuncAttributeMaxDynamicSharedMemorySize, GEMM_SMEM);
    cudaFuncSetAttribute(attn_tc,   cudaFuncAttributeMaxDynamicSharedMemorySize, ATT_SMEM);

    round_x<<<(B_ * T_ * E_) / 1024, 256>>>(x);
    tr_wqkv<<<dim3(E_ / 64, H_, 3), 256>>>(wq, wk, wv);
    tr_wp<<<dim3(E_ / 64, E_ / 64), 256>>>(wp);
    qkv_gemm<<<dim3((B_ * T_) / 128, (3 * NH) / 128), 128, GEMM_SMEM>>>();
    attn_tc<<<dim3(T_ / 128, H_, B_), 128, ATT_SMEM>>>();
    proj_gemm<<<dim3((B_ * T_) / 128, E_ / 128), 128, GEMM_SMEM>>>(out);
}